// round 14
// baseline (speedup 1.0000x reference)
#include <cuda_runtime.h>
#include <cstdint>

#define T_LEN   4096
#define BATCH   512
#define NTHR    256
#define WPB     (NTHR / 32)        // 8 warps per block
#define CHUNKS  16
#define CSZ     (T_LEN / CHUNKS)   // 256 timesteps per warp (8 per lane)
#define TILE    128
#define NC0BLK  64                 // dedicated blocks for all chunk-0 warps (64*8 = 512)
#define DT      0.005f
#define RS      64.0f              // rescale for linearized Riccati chain

// Grid-wide reduction scratch (reset by last block each launch -> graph-replay safe)
__device__ double       g_sum = 0.0;
__device__ unsigned int g_cnt = 0u;

__device__ __forceinline__ float shup(float v, int o)  { return __shfl_up_sync(0xffffffffu, v, o); }
__device__ __forceinline__ float shdn(float v, int o)  { return __shfl_down_sync(0xffffffffu, v, o); }
__device__ __forceinline__ float bcast(float v, int l) { return __shfl_sync(0xffffffffu, v, l); }

extern "C" __global__ void __launch_bounds__(NTHR, 3)
kf_loss_kernel(const float* __restrict__ pred_vel,
               const float* __restrict__ targ_vel,
               const float* __restrict__ q_vel_p,
               const float* __restrict__ r_vel_p,
               float* __restrict__ out)
{
    __shared__ float swsum[WPB];

    const int tid  = threadIdx.x;
    const int lane = tid & 31;
    const int wid  = tid >> 5;
    const int bid  = blockIdx.x;

    // ---- homogeneous-block mapping: bid<64 -> chunk-0 warps only ----
    int row, chunk;
    if (bid < NC0BLK) {
        row = bid * WPB + wid;                 // 0..511
        chunk = 0;
    } else {
        int wg2 = (bid - NC0BLK) * WPB + wid;  // 0..7679
        row = wg2 / 15;
        chunk = 1 + (wg2 - 15 * row);          // 1..15
    }
    const int c0 = chunk * CSZ;

    const float2* __restrict__ zr = (const float2*)pred_vel + (size_t)row * T_LEN;
    const float2* __restrict__ wr = (const float2*)targ_vel + (size_t)row * T_LEN;

    const float qv = __ldg(q_vel_p);
    const float r  = __ldg(r_vel_p);

    // ============ front-batch EVERY load of this chunk ============
    float4 za, zb, zc, zd, wa, wb, wc, wd;   // steady: 8 steps/lane (256-step tile)
    float2 hz;                               // halo (chunk>0)
    float2 tz0, tz1, tz2, tz3;               // table z       (chunk 0)
    float2 tw0, tw1, tw2, tw3;               // table w@t+1   (chunk 0)
    float4 zaA, zbA, waA, wbA;               // chunk-0 steady tile [128,256), 4/lane

    if (chunk == 0) {
        tz0 = zr[lane];          tz1 = zr[32 + lane];
        tz2 = zr[64 + lane];     tz3 = zr[96 + lane];
        tw0 = wr[lane + 1];      tw1 = wr[32 + lane + 1];
        tw2 = wr[64 + lane + 1]; tw3 = wr[96 + lane + 1];
        const float4* z4 = (const float4*)(zr + TILE);
        const float4* w4 = (const float4*)(wr + TILE);
        zaA = z4[2 * lane]; zbA = z4[2 * lane + 1];
        waA = w4[2 * lane]; wbA = w4[2 * lane + 1];
    } else {
        const float4* z4 = (const float4*)(zr + c0);
        const float4* w4 = (const float4*)(wr + c0);
        za = z4[4 * lane];     zb = z4[4 * lane + 1];
        zc = z4[4 * lane + 2]; zd = z4[4 * lane + 3];
        wa = w4[4 * lane];     wb = w4[4 * lane + 1];
        wc = w4[4 * lane + 2]; wd = w4[4 * lane + 3];
        hz = zr[c0 - 32 + lane];
    }

    // ============ steady-state gains: closed form ============
    const float cp = 0.5f * (qv + sqrtf(fmaf(qv, qv, 4.0f * qv * r)));
    const float K1 = __fdividef(cp, cp + r);
    const float K0 = DT * (1.0f - __fdividef(qv, cp));

    const float dss  = 1.0f - K1;          // v <- dss*v + K1*z
    const float Ass  = DT - K0;            // e = Ass*v - DT*w1 + K0*z1
    const float dss2 = dss * dss, dss3 = dss2 * dss, dss4 = dss2 * dss2;
    const float dss5 = dss4 * dss, dss6 = dss4 * dss2, dss7 = dss4 * dss3;
    const float e2  = dss4 * dss4;         // dss^8
    const float e4  = e2 * e2;             // dss^16
    const float e8  = e4 * e4;             // dss^32
    const float e16 = e8 * e8;             // dss^64

    float cx = 0.0f, cy = 0.0f;
    float acc = 0.0f;

    if (chunk == 0) {
        // ===== per-lane gain table via linearized Riccati (64 dedicated blocks) =====
        float dl4 = 1.0f;                  // dss^(4*lane) for the 4/lane steady tile
        if (lane & 1)  dl4 *= dss4;
        if (lane & 2)  dl4 *= e2;
        if (lane & 4)  dl4 *= e4;
        if (lane & 8)  dl4 *= e8;
        if (lane & 16) dl4 *= e16;

        const float c_xy = RS * r, c_xq = RS * qv * r, c_yy = RS * (qv + r), c_u = RS * r;
        float x = 1.0f, y = 1.0f, u = 0.0f;
        for (int t = 0; t < lane; ++t) {
            float xn = fmaf(c_xq, y, c_xy * x);
            float yn = fmaf(c_yy, y, RS * x);
            float un = c_u * fmaf(DT, x, u);
            x = xn; y = yn; u = un;
        }
        float k1t[4], k0t[4];                       // gains at t = 32*it + lane
        #pragma unroll
        for (int it = 0; it < 4; ++it) {
            float xs = x, ys = y, us = u;
            { float xn = fmaf(c_xq, y, c_xy * x);
              float yn = fmaf(c_yy, y, RS * x);
              float un = c_u * fmaf(DT, x, u);
              x = xn; y = yn; u = un; }
            float inv = __fdividef(RS, y);
            k1t[it] = fmaf(qv, ys, xs) * inv;
            k0t[it] = fmaf(DT, xs, us) * inv;
            if (it < 3)
                for (int t = 0; t < 31; ++t) {
                    float xn = fmaf(c_xq, y, c_xy * x);
                    float yn = fmaf(c_yy, y, RS * x);
                    float un = c_u * fmaf(DT, x, u);
                    x = xn; y = yn; u = un;
                }
        }

        // ===== table region: errors at t in [0,127), v via variable-coef scans =====
        #pragma unroll
        for (int it = 0; it < 4; ++it) {
            float2 z  = (it == 0) ? tz0 : (it == 1) ? tz1 : (it == 2) ? tz2 : tz3;
            float2 w1 = (it == 0) ? tw0 : (it == 1) ? tw1 : (it == 2) ? tw2 : tw3;
            float K1v = k1t[it];
            float p   = 1.0f - K1v;
            float sx = K1v * z.x, sy = K1v * z.y;
            #pragma unroll
            for (int o = 1; o < 32; o <<= 1) {
                float ax = shup(sx, o), ay = shup(sy, o), ap = shup(p, o);
                if (lane >= o) { sx = fmaf(p, ax, sx); sy = fmaf(p, ay, sy); p *= ap; }
            }
            float vx = fmaf(p, cx, sx);
            float vy = fmaf(p, cy, sy);
            cx = bcast(vx, 31); cy = bcast(vy, 31);

            // error at t = 32*it + lane (needs t+1 data; all collectives hoisted)
            float k0n = shdn(k0t[it], 1);
            float k0w = (it < 3) ? bcast(k0t[it + 1], 0) : K0;
            float z1x = shdn(z.x, 1), z1y = shdn(z.y, 1);
            float zwx = (it == 0) ? bcast(tz1.x, 0) : (it == 1) ? bcast(tz2.x, 0)
                      : (it == 2) ? bcast(tz3.x, 0) : bcast(zaA.x, 0);
            float zwy = (it == 0) ? bcast(tz1.y, 0) : (it == 1) ? bcast(tz2.y, 0)
                      : (it == 2) ? bcast(tz3.y, 0) : bcast(zaA.y, 0);
            if (lane == 31) { k0n = k0w; z1x = zwx; z1y = zwy; }
            float an = DT - k0n;

            float ex = fmaf(an, vx, fmaf(-DT, w1.x, k0n * z1x));
            float ey = fmaf(an, vy, fmaf(-DT, w1.y, k0n * z1y));
            if (!(it == 3 && lane == 31)) {     // t=127 belongs to the steady tile below
                acc = fmaf(ex, ex, acc);
                acc = fmaf(ey, ey, acc);
            }
        }

        // ===== steady 4/lane tile [128,256): errors [127,255); exact carry cx=v_127 =====
        {
            float s0x = K1 * zaA.x, s0y = K1 * zaA.y;
            float s1x = fmaf(dss, s0x, K1 * zaA.z), s1y = fmaf(dss, s0y, K1 * zaA.w);
            float s2x = fmaf(dss, s1x, K1 * zbA.x), s2y = fmaf(dss, s1y, K1 * zbA.y);
            float s3x = fmaf(dss, s2x, K1 * zbA.z), s3y = fmaf(dss, s2y, K1 * zbA.w);
            float Sx = s3x, Sy = s3y, t1_;
            t1_ = shup(Sx, 1); if (lane >= 1) Sx = fmaf(dss4, t1_, Sx);
            t1_ = shup(Sy, 1); if (lane >= 1) Sy = fmaf(dss4, t1_, Sy);
            t1_ = shup(Sx, 2); if (lane >= 2) Sx = fmaf(e2, t1_, Sx);
            t1_ = shup(Sy, 2); if (lane >= 2) Sy = fmaf(e2, t1_, Sy);
            t1_ = shup(Sx, 4); if (lane >= 4) Sx = fmaf(e4, t1_, Sx);
            t1_ = shup(Sy, 4); if (lane >= 4) Sy = fmaf(e4, t1_, Sy);
            float Px = shup(Sx, 1), Py = shup(Sy, 1);
            if (lane == 0) { Px = 0.0f; Py = 0.0f; }
            float dl4_ = dl4;
            float prx = fmaf(dl4_, cx, Px);        // v at i0-1
            float pry = fmaf(dl4_, cy, Py);
            float v0x = fmaf(dss,  prx, s0x), v0y = fmaf(dss,  pry, s0y);
            float v1x = fmaf(dss2, prx, s1x), v1y = fmaf(dss2, pry, s1y);
            float v2x = fmaf(dss3, prx, s2x), v2y = fmaf(dss3, pry, s2y);
            float ex_, ey_;
            ex_ = fmaf(Ass, prx, fmaf(-DT, waA.x, K0 * zaA.x));
            ey_ = fmaf(Ass, pry, fmaf(-DT, waA.y, K0 * zaA.y));
            acc = fmaf(ex_, ex_, acc); acc = fmaf(ey_, ey_, acc);
            ex_ = fmaf(Ass, v0x, fmaf(-DT, waA.z, K0 * zaA.z));
            ey_ = fmaf(Ass, v0y, fmaf(-DT, waA.w, K0 * zaA.w));
            acc = fmaf(ex_, ex_, acc); acc = fmaf(ey_, ey_, acc);
            ex_ = fmaf(Ass, v1x, fmaf(-DT, wbA.x, K0 * zbA.x));
            ey_ = fmaf(Ass, v1y, fmaf(-DT, wbA.y, K0 * zbA.y));
            acc = fmaf(ex_, ex_, acc); acc = fmaf(ey_, ey_, acc);
            ex_ = fmaf(Ass, v2x, fmaf(-DT, wbA.z, K0 * zbA.z));
            ey_ = fmaf(Ass, v2y, fmaf(-DT, wbA.w, K0 * zbA.w));
            acc = fmaf(ex_, ex_, acc); acc = fmaf(ey_, ey_, acc);
        }
    } else {
        // ===== halo: 32-step steady scan -> carry v_{c0-1} =====
        float sx = K1 * hz.x, sy = K1 * hz.y, t1;
        t1 = shup(sx, 1);  if (lane >= 1)  sx = fmaf(dss,  t1, sx);
        t1 = shup(sy, 1);  if (lane >= 1)  sy = fmaf(dss,  t1, sy);
        t1 = shup(sx, 2);  if (lane >= 2)  sx = fmaf(dss2, t1, sx);
        t1 = shup(sy, 2);  if (lane >= 2)  sy = fmaf(dss2, t1, sy);
        t1 = shup(sx, 4);  if (lane >= 4)  sx = fmaf(dss4, t1, sx);
        t1 = shup(sy, 4);  if (lane >= 4)  sy = fmaf(dss4, t1, sy);
        t1 = shup(sx, 8);  if (lane >= 8)  sx = fmaf(e2,   t1, sx);
        t1 = shup(sy, 8);  if (lane >= 8)  sy = fmaf(e2,   t1, sy);
        t1 = shup(sx, 16); if (lane >= 16) sx = fmaf(e4,   t1, sx);
        t1 = shup(sy, 16); if (lane >= 16) sy = fmaf(e4,   t1, sy);
        cx = bcast(sx, 31); cy = bcast(sy, 31);

        // ===== one 256-step tile, 8 steps/lane: errors [c0-1, c0+255) =====
        float dl8 = 1.0f;                  // dss^(8*lane): carry-injection weight
        if (lane & 1)  dl8 *= e2;
        if (lane & 2)  dl8 *= e4;
        if (lane & 4)  dl8 *= e8;
        if (lane & 8)  dl8 *= e16;
        if (lane & 16) dl8 *= e16 * e16;

        // local 8-step prefix (two independent x/y chains, 4-cyc links)
        float s0x = K1 * za.x, s0y = K1 * za.y;
        float s1x = fmaf(dss, s0x, K1 * za.z), s1y = fmaf(dss, s0y, K1 * za.w);
        float s2x = fmaf(dss, s1x, K1 * zb.x), s2y = fmaf(dss, s1y, K1 * zb.y);
        float s3x = fmaf(dss, s2x, K1 * zb.z), s3y = fmaf(dss, s2y, K1 * zb.w);
        float s4x = fmaf(dss, s3x, K1 * zc.x), s4y = fmaf(dss, s3y, K1 * zc.y);
        float s5x = fmaf(dss, s4x, K1 * zc.z), s5y = fmaf(dss, s4y, K1 * zc.w);
        float s6x = fmaf(dss, s5x, K1 * zd.x), s6y = fmaf(dss, s5y, K1 * zd.y);
        float s7x = fmaf(dss, s6x, K1 * zd.z), s7y = fmaf(dss, s6y, K1 * zd.w);

        // 3-step scan over lane blocks (coefs dss^8, dss^16, dss^32; >=dss^64 dropped)
        float Sx = s7x, Sy = s7y, t2;
        t2 = shup(Sx, 1); if (lane >= 1) Sx = fmaf(e2, t2, Sx);
        t2 = shup(Sy, 1); if (lane >= 1) Sy = fmaf(e2, t2, Sy);
        t2 = shup(Sx, 2); if (lane >= 2) Sx = fmaf(e4, t2, Sx);
        t2 = shup(Sy, 2); if (lane >= 2) Sy = fmaf(e4, t2, Sy);
        t2 = shup(Sx, 4); if (lane >= 4) Sx = fmaf(e8, t2, Sx);
        t2 = shup(Sy, 4); if (lane >= 4) Sy = fmaf(e8, t2, Sy);

        float Px = shup(Sx, 1), Py = shup(Sy, 1);
        if (lane == 0) { Px = 0.0f; Py = 0.0f; }
        float prx = fmaf(dl8, cx, Px);            // v at i0-1 (i0 = c0 + 8*lane)
        float pry = fmaf(dl8, cy, Py);

        float v0x = fmaf(dss,  prx, s0x), v0y = fmaf(dss,  pry, s0y);
        float v1x = fmaf(dss2, prx, s1x), v1y = fmaf(dss2, pry, s1y);
        float v2x = fmaf(dss3, prx, s2x), v2y = fmaf(dss3, pry, s2y);
        float v3x = fmaf(dss4, prx, s3x), v3y = fmaf(dss4, pry, s3y);
        float v4x = fmaf(dss5, prx, s4x), v4y = fmaf(dss5, pry, s4y);
        float v5x = fmaf(dss6, prx, s5x), v5y = fmaf(dss6, pry, s5y);
        float v6x = fmaf(dss7, prx, s6x), v6y = fmaf(dss7, pry, s6y);

        // 8 lane-local errors (shifted indexing: i = i0-1 .. i0+6); no guards needed
        float ex_, ey_;
        ex_ = fmaf(Ass, prx, fmaf(-DT, wa.x, K0 * za.x));
        ey_ = fmaf(Ass, pry, fmaf(-DT, wa.y, K0 * za.y));
        acc = fmaf(ex_, ex_, acc); acc = fmaf(ey_, ey_, acc);
        ex_ = fmaf(Ass, v0x, fmaf(-DT, wa.z, K0 * za.z));
        ey_ = fmaf(Ass, v0y, fmaf(-DT, wa.w, K0 * za.w));
        acc = fmaf(ex_, ex_, acc); acc = fmaf(ey_, ey_, acc);
        ex_ = fmaf(Ass, v1x, fmaf(-DT, wb.x, K0 * zb.x));
        ey_ = fmaf(Ass, v1y, fmaf(-DT, wb.y, K0 * zb.y));
        acc = fmaf(ex_, ex_, acc); acc = fmaf(ey_, ey_, acc);
        ex_ = fmaf(Ass, v2x, fmaf(-DT, wb.z, K0 * zb.z));
        ey_ = fmaf(Ass, v2y, fmaf(-DT, wb.w, K0 * zb.w));
        acc = fmaf(ex_, ex_, acc); acc = fmaf(ey_, ey_, acc);
        ex_ = fmaf(Ass, v3x, fmaf(-DT, wc.x, K0 * zc.x));
        ey_ = fmaf(Ass, v3y, fmaf(-DT, wc.y, K0 * zc.y));
        acc = fmaf(ex_, ex_, acc); acc = fmaf(ey_, ey_, acc);
        ex_ = fmaf(Ass, v4x, fmaf(-DT, wc.z, K0 * zc.z));
        ey_ = fmaf(Ass, v4y, fmaf(-DT, wc.w, K0 * zc.w));
        acc = fmaf(ex_, ex_, acc); acc = fmaf(ey_, ey_, acc);
        ex_ = fmaf(Ass, v5x, fmaf(-DT, wd.x, K0 * zd.x));
        ey_ = fmaf(Ass, v5y, fmaf(-DT, wd.y, K0 * zd.y));
        acc = fmaf(ex_, ex_, acc); acc = fmaf(ey_, ey_, acc);
        ex_ = fmaf(Ass, v6x, fmaf(-DT, wd.z, K0 * zd.z));
        ey_ = fmaf(Ass, v6y, fmaf(-DT, wd.w, K0 * zd.w));
        acc = fmaf(ex_, ex_, acc); acc = fmaf(ey_, ey_, acc);
    }

    // ============ reduction ============
    #pragma unroll
    for (int o = 16; o > 0; o >>= 1)
        acc += __shfl_xor_sync(0xffffffffu, acc, o);
    if (lane == 0) swsum[wid] = acc;
    __syncthreads();

    if (tid == 0) {
        float bs = 0.0f;
        #pragma unroll
        for (int i = 0; i < WPB; ++i) bs += swsum[i];

        atomicAdd(&g_sum, (double)bs);
        __threadfence();
        unsigned c = atomicAdd(&g_cnt, 1u);
        if (c == gridDim.x - 1) {
            double s = atomicAdd(&g_sum, 0.0);        // coherent read (includes own add)
            const double cnt = (double)BATCH * (double)(T_LEN - 1) * 2.0;
            out[0] = (float)(s / cnt);
            g_sum = 0.0;                              // reset for next graph replay
            g_cnt = 0u;
        }
    }
}

extern "C" void kernel_launch(void* const* d_in, const int* in_sizes, int n_in,
                              void* d_out, int out_size)
{
    const float* pred_vel = (const float*)d_in[0];   // (B, T, 2)
    const float* targ_vel = (const float*)d_in[1];   // (B, T, 2)
    // d_in[2] = q_pos (never feeds the gain recursion)
    const float* q_vel    = (const float*)d_in[3];
    const float* r_vel    = (const float*)d_in[4];
    // d_in[5] = p0 (cancels in the windowed position difference)
    float* out = (float*)d_out;

    const int nblocks = NC0BLK + (BATCH * 15) / WPB;   // 64 + 960 = 1024 blocks
    kf_loss_kernel<<<nblocks, NTHR>>>(pred_vel, targ_vel, q_vel, r_vel, out);
}

// round 15
// speedup vs baseline: 1.1130x; 1.1130x over previous
#include <cuda_runtime.h>
#include <cstdint>

#define T_LEN   4096
#define BATCH   512
#define NTHR    256
#define WPB     (NTHR / 32)        // 8 warps per block
#define CHUNKS  16
#define CSZ     (T_LEN / CHUNKS)   // 256 timesteps per warp
#define NC0BLK  64                 // dedicated blocks for all chunk-0 warps (64*8 = 512)
#define DT      0.005f
#define RS      64.0f              // rescale for linearized Riccati chain

// Grid-wide reduction scratch (reset by last block each launch -> graph-replay safe)
__device__ double       g_sum = 0.0;
__device__ unsigned int g_cnt = 0u;

__device__ __forceinline__ float shup(float v, int o)  { return __shfl_up_sync(0xffffffffu, v, o); }
__device__ __forceinline__ float shdn(float v, int o)  { return __shfl_down_sync(0xffffffffu, v, o); }
__device__ __forceinline__ float bcast(float v, int l) { return __shfl_sync(0xffffffffu, v, l); }

extern "C" __global__ void __launch_bounds__(NTHR, 4)
kf_loss_kernel(const float* __restrict__ pred_vel,
               const float* __restrict__ targ_vel,
               const float* __restrict__ q_vel_p,
               const float* __restrict__ r_vel_p,
               float* __restrict__ out)
{
    __shared__ float swsum[WPB];

    const int tid  = threadIdx.x;
    const int lane = tid & 31;
    const int wid  = tid >> 5;
    const int bid  = blockIdx.x;

    // ---- homogeneous-block mapping: bid<64 -> chunk-0 warps only ----
    int row, chunk;
    if (bid < NC0BLK) {
        row = bid * WPB + wid;                 // 0..511
        chunk = 0;
    } else {
        int wg2 = (bid - NC0BLK) * WPB + wid;  // 0..7679
        row = wg2 / 15;
        chunk = 1 + (wg2 - 15 * row);          // 1..15
    }
    const int c0 = chunk * CSZ;

    const float2* __restrict__ zr = (const float2*)pred_vel + (size_t)row * T_LEN;
    const float2* __restrict__ wr = (const float2*)targ_vel + (size_t)row * T_LEN;

    const float qv = __ldg(q_vel_p);
    const float r  = __ldg(r_vel_p);

    // ============ front-batch EVERY load, ALL perfectly coalesced ============
    // z4[32*s + lane]: warp request = 512 B contiguous = 4 lines (minimum wavefronts).
    // Each float4 = 2 consecutive timesteps for this lane.
    float4 z0, z1, z2, z3, w0, w1, w2, w3;
    float2 hz;                               // halo (chunk>0)
    float2 tz0, tz1, tz2, tz3;               // table z       (chunk 0)
    float2 tw0, tw1, tw2, tw3;               // table w@t+1   (chunk 0)

    if (chunk == 0) {
        tz0 = zr[lane];          tz1 = zr[32 + lane];
        tz2 = zr[64 + lane];     tz3 = zr[96 + lane];
        tw0 = wr[lane + 1];      tw1 = wr[32 + lane + 1];
        tw2 = wr[64 + lane + 1]; tw3 = wr[96 + lane + 1];
        const float4* z4 = (const float4*)zr;
        const float4* w4 = (const float4*)wr;
        z2 = z4[64 + lane]; z3 = z4[96 + lane];     // steps [128,192) [192,256)
        w2 = w4[64 + lane]; w3 = w4[96 + lane];
    } else {
        const float4* z4 = (const float4*)(zr + c0);
        const float4* w4 = (const float4*)(wr + c0);
        z0 = z4[lane];      z1 = z4[32 + lane];
        z2 = z4[64 + lane]; z3 = z4[96 + lane];
        w0 = w4[lane];      w1 = w4[32 + lane];
        w2 = w4[64 + lane]; w3 = w4[96 + lane];
        hz = zr[c0 - 32 + lane];
    }

    // ============ steady-state gains: closed form ============
    const float cp = 0.5f * (qv + sqrtf(fmaf(qv, qv, 4.0f * qv * r)));
    const float K1 = __fdividef(cp, cp + r);
    const float K0 = DT * (1.0f - __fdividef(qv, cp));

    const float dss  = 1.0f - K1;          // v <- dss*v + K1*z
    const float Ass  = DT - K0;            // e = Ass*v - DT*w1 + K0*z1
    const float dss2 = dss * dss, dss4 = dss2 * dss2;
    const float e2  = dss4 * dss4;         // dss^8
    const float e4  = e2 * e2;             // dss^16
    const float e8  = e4 * e4;             // dss^32
    float dl2 = 1.0f;                      // dss^(2*lane): carry-injection weight
    if (lane & 1)  dl2 *= dss2;
    if (lane & 2)  dl2 *= dss4;
    if (lane & 4)  dl2 *= e2;
    if (lane & 8)  dl2 *= e4;
    if (lane & 16) dl2 *= e8;

    float cx = 0.0f, cy = 0.0f;
    float acc = 0.0f;

    // ============ steady 64-step subtile: 2 steps/lane, errors {i0-1, i0} ============
    // i0 = base + 2*lane. Scan offsets 1,2,4,8 (coefs dss^2..dss^16) -> 32-step
    // effective history (validated truncation). Carry = bcast only (dss^64 dropped).
    #define STEADY64(Z, W)                                                                \
    {                                                                                     \
        float s0x = K1 * (Z).x, s0y = K1 * (Z).y;                                         \
        float s1x = fmaf(dss, s0x, K1 * (Z).z), s1y = fmaf(dss, s0y, K1 * (Z).w);         \
        float Sx = s1x, Sy = s1y, t_;                                                     \
        t_ = shup(Sx, 1); if (lane >= 1) Sx = fmaf(dss2, t_, Sx);                         \
        t_ = shup(Sy, 1); if (lane >= 1) Sy = fmaf(dss2, t_, Sy);                         \
        t_ = shup(Sx, 2); if (lane >= 2) Sx = fmaf(dss4, t_, Sx);                         \
        t_ = shup(Sy, 2); if (lane >= 2) Sy = fmaf(dss4, t_, Sy);                         \
        t_ = shup(Sx, 4); if (lane >= 4) Sx = fmaf(e2, t_, Sx);                           \
        t_ = shup(Sy, 4); if (lane >= 4) Sy = fmaf(e2, t_, Sy);                           \
        t_ = shup(Sx, 8); if (lane >= 8) Sx = fmaf(e4, t_, Sx);                           \
        t_ = shup(Sy, 8); if (lane >= 8) Sy = fmaf(e4, t_, Sy);                           \
        float Px = shup(Sx, 1), Py = shup(Sy, 1);                                         \
        if (lane == 0) { Px = 0.0f; Py = 0.0f; }                                          \
        float prx = fmaf(dl2, cx, Px);        /* v at i0-1 */                             \
        float pry = fmaf(dl2, cy, Py);                                                    \
        cx = bcast(Sx, 31);                                                               \
        cy = bcast(Sy, 31);                                                               \
        float v0x = fmaf(dss, prx, s0x), v0y = fmaf(dss, pry, s0y);                       \
        float ex_, ey_;                                                                   \
        ex_ = fmaf(Ass, prx, fmaf(-DT, (W).x, K0 * (Z).x));   /* i = i0-1 */              \
        ey_ = fmaf(Ass, pry, fmaf(-DT, (W).y, K0 * (Z).y));                               \
        acc = fmaf(ex_, ex_, acc); acc = fmaf(ey_, ey_, acc);                             \
        ex_ = fmaf(Ass, v0x, fmaf(-DT, (W).z, K0 * (Z).z));   /* i = i0   */              \
        ey_ = fmaf(Ass, v0y, fmaf(-DT, (W).w, K0 * (Z).w));                               \
        acc = fmaf(ex_, ex_, acc); acc = fmaf(ey_, ey_, acc);                             \
    }

    if (chunk == 0) {
        // ===== per-lane gain table via linearized Riccati (64 dedicated blocks) =====
        const float c_xy = RS * r, c_xq = RS * qv * r, c_yy = RS * (qv + r), c_u = RS * r;
        float x = 1.0f, y = 1.0f, u = 0.0f;
        for (int t = 0; t < lane; ++t) {
            float xn = fmaf(c_xq, y, c_xy * x);
            float yn = fmaf(c_yy, y, RS * x);
            float un = c_u * fmaf(DT, x, u);
            x = xn; y = yn; u = un;
        }
        float k1t[4], k0t[4];                       // gains at t = 32*it + lane
        #pragma unroll
        for (int it = 0; it < 4; ++it) {
            float xs = x, ys = y, us = u;
            { float xn = fmaf(c_xq, y, c_xy * x);
              float yn = fmaf(c_yy, y, RS * x);
              float un = c_u * fmaf(DT, x, u);
              x = xn; y = yn; u = un; }
            float inv = __fdividef(RS, y);
            k1t[it] = fmaf(qv, ys, xs) * inv;
            k0t[it] = fmaf(DT, xs, us) * inv;
            if (it < 3)
                for (int t = 0; t < 31; ++t) {
                    float xn = fmaf(c_xq, y, c_xy * x);
                    float yn = fmaf(c_yy, y, RS * x);
                    float un = c_u * fmaf(DT, x, u);
                    x = xn; y = yn; u = un;
                }
        }

        // ===== table region: errors at t in [0,127), v via variable-coef scans =====
        #pragma unroll
        for (int it = 0; it < 4; ++it) {
            float2 z  = (it == 0) ? tz0 : (it == 1) ? tz1 : (it == 2) ? tz2 : tz3;
            float2 w1 = (it == 0) ? tw0 : (it == 1) ? tw1 : (it == 2) ? tw2 : tw3;
            float K1v = k1t[it];
            float p   = 1.0f - K1v;
            float sx = K1v * z.x, sy = K1v * z.y;
            #pragma unroll
            for (int o = 1; o < 32; o <<= 1) {
                float ax = shup(sx, o), ay = shup(sy, o), ap = shup(p, o);
                if (lane >= o) { sx = fmaf(p, ax, sx); sy = fmaf(p, ay, sy); p *= ap; }
            }
            float vx = fmaf(p, cx, sx);
            float vy = fmaf(p, cy, sy);
            cx = bcast(vx, 31); cy = bcast(vy, 31);

            // error at t = 32*it + lane (needs t+1 data; all collectives hoisted)
            float k0n = shdn(k0t[it], 1);
            float k0w = (it < 3) ? bcast(k0t[it + 1], 0) : K0;
            float z1x = shdn(z.x, 1), z1y = shdn(z.y, 1);
            float zwx = (it == 0) ? bcast(tz1.x, 0) : (it == 1) ? bcast(tz2.x, 0)
                      : (it == 2) ? bcast(tz3.x, 0) : bcast(z2.x, 0);
            float zwy = (it == 0) ? bcast(tz1.y, 0) : (it == 1) ? bcast(tz2.y, 0)
                      : (it == 2) ? bcast(tz3.y, 0) : bcast(z2.y, 0);
            if (lane == 31) { k0n = k0w; z1x = zwx; z1y = zwy; }
            float an = DT - k0n;

            float ex = fmaf(an, vx, fmaf(-DT, w1.x, k0n * z1x));
            float ey = fmaf(an, vy, fmaf(-DT, w1.y, k0n * z1y));
            if (!(it == 3 && lane == 31)) {     // t=127 belongs to the steady subtiles
                acc = fmaf(ex, ex, acc);
                acc = fmaf(ey, ey, acc);
            }
        }
        // steady subtiles [128,192) [192,256): errors [127,255); exact carry cx=v_127
        STEADY64(z2, w2)
        STEADY64(z3, w3)
    } else {
        // ===== halo: 32-step steady scan -> carry v_{c0-1} (validated truncation) =====
        float sx = K1 * hz.x, sy = K1 * hz.y, t1;
        t1 = shup(sx, 1);  if (lane >= 1)  sx = fmaf(dss,  t1, sx);
        t1 = shup(sy, 1);  if (lane >= 1)  sy = fmaf(dss,  t1, sy);
        t1 = shup(sx, 2);  if (lane >= 2)  sx = fmaf(dss2, t1, sx);
        t1 = shup(sy, 2);  if (lane >= 2)  sy = fmaf(dss2, t1, sy);
        t1 = shup(sx, 4);  if (lane >= 4)  sx = fmaf(dss4, t1, sx);
        t1 = shup(sy, 4);  if (lane >= 4)  sy = fmaf(dss4, t1, sy);
        t1 = shup(sx, 8);  if (lane >= 8)  sx = fmaf(e2,   t1, sx);
        t1 = shup(sy, 8);  if (lane >= 8)  sy = fmaf(e2,   t1, sy);
        t1 = shup(sx, 16); if (lane >= 16) sx = fmaf(e4,   t1, sx);
        t1 = shup(sy, 16); if (lane >= 16) sy = fmaf(e4,   t1, sy);
        cx = bcast(sx, 31); cy = bcast(sy, 31);

        // 4 steady subtiles: errors [c0-1, c0+255)
        STEADY64(z0, w0)
        STEADY64(z1, w1)
        STEADY64(z2, w2)
        STEADY64(z3, w3)
    }
    #undef STEADY64

    // ============ reduction ============
    #pragma unroll
    for (int o = 16; o > 0; o >>= 1)
        acc += __shfl_xor_sync(0xffffffffu, acc, o);
    if (lane == 0) swsum[wid] = acc;
    __syncthreads();

    if (tid == 0) {
        float bs = 0.0f;
        #pragma unroll
        for (int i = 0; i < WPB; ++i) bs += swsum[i];

        atomicAdd(&g_sum, (double)bs);
        __threadfence();
        unsigned c = atomicAdd(&g_cnt, 1u);
        if (c == gridDim.x - 1) {
            double s = atomicAdd(&g_sum, 0.0);        // coherent read (includes own add)
            const double cnt = (double)BATCH * (double)(T_LEN - 1) * 2.0;
            out[0] = (float)(s / cnt);
            g_sum = 0.0;                              // reset for next graph replay
            g_cnt = 0u;
        }
    }
}

extern "C" void kernel_launch(void* const* d_in, const int* in_sizes, int n_in,
                              void* d_out, int out_size)
{
    const float* pred_vel = (const float*)d_in[0];   // (B, T, 2)
    const float* targ_vel = (const float*)d_in[1];   // (B, T, 2)
    // d_in[2] = q_pos (never feeds the gain recursion)
    const float* q_vel    = (const float*)d_in[3];
    const float* r_vel    = (const float*)d_in[4];
    // d_in[5] = p0 (cancels in the windowed position difference)
    float* out = (float*)d_out;

    const int nblocks = NC0BLK + (BATCH * 15) / WPB;   // 64 + 960 = 1024 blocks
    kf_loss_kernel<<<nblocks, NTHR>>>(pred_vel, targ_vel, q_vel, r_vel, out);
}

// round 16
// speedup vs baseline: 1.1604x; 1.0426x over previous
#include <cuda_runtime.h>
#include <cstdint>

#define T_LEN   4096
#define BATCH   512
#define NTHR    256
#define WPB     (NTHR / 32)        // 8 warps per block
#define CHUNKS  16
#define CSZ     (T_LEN / CHUNKS)   // 256 timesteps per warp
#define NC0BLK  64                 // dedicated blocks for all chunk-0 warps (64*8 = 512)
#define DT      0.005f
#define RS      64.0f              // rescale for linearized Riccati chain

// Grid-wide reduction scratch (reset by last block each launch -> graph-replay safe)
__device__ double       g_sum = 0.0;
__device__ unsigned int g_cnt = 0u;

typedef unsigned long long u64;

__device__ __forceinline__ float shup(float v, int o)  { return __shfl_up_sync(0xffffffffu, v, o); }
__device__ __forceinline__ float shdn(float v, int o)  { return __shfl_down_sync(0xffffffffu, v, o); }
__device__ __forceinline__ float bcast(float v, int l) { return __shfl_sync(0xffffffffu, v, l); }

// ---- packed f32x2 helpers (FFMA2 path: only reachable via explicit PTX) ----
__device__ __forceinline__ u64 pk2(float lo, float hi) {
    u64 r; asm("mov.b64 %0, {%1, %2};" : "=l"(r) : "f"(lo), "f"(hi)); return r;
}
__device__ __forceinline__ void unpk2(u64 v, float& lo, float& hi) {
    asm("mov.b64 {%0, %1}, %2;" : "=f"(lo), "=f"(hi) : "l"(v));
}
__device__ __forceinline__ u64 dup2(float v) { return pk2(v, v); }
__device__ __forceinline__ u64 fma2(u64 a, u64 b, u64 c) {
    u64 d; asm("fma.rn.f32x2 %0, %1, %2, %3;" : "=l"(d) : "l"(a), "l"(b), "l"(c)); return d;
}
__device__ __forceinline__ u64 mul2(u64 a, u64 b) {
    u64 d; asm("mul.rn.f32x2 %0, %1, %2;" : "=l"(d) : "l"(a), "l"(b)); return d;
}
__device__ __forceinline__ u64 shup64(u64 v, int o) { return __shfl_up_sync(0xffffffffu, v, o); }
__device__ __forceinline__ u64 bc64(u64 v, int l)   { return __shfl_sync(0xffffffffu, v, l); }

extern "C" __global__ void __launch_bounds__(NTHR, 3)
kf_loss_kernel(const float* __restrict__ pred_vel,
               const float* __restrict__ targ_vel,
               const float* __restrict__ q_vel_p,
               const float* __restrict__ r_vel_p,
               float* __restrict__ out)
{
    __shared__ float swsum[WPB];

    const int tid  = threadIdx.x;
    const int lane = tid & 31;
    const int wid  = tid >> 5;
    const int bid  = blockIdx.x;

    // ---- homogeneous-block mapping: bid<64 -> chunk-0 warps only ----
    int row, chunk;
    if (bid < NC0BLK) {
        row = bid * WPB + wid;                 // 0..511
        chunk = 0;
    } else {
        int wg2 = (bid - NC0BLK) * WPB + wid;  // 0..7679
        row = wg2 / 15;
        chunk = 1 + (wg2 - 15 * row);          // 1..15
    }
    const int c0 = chunk * CSZ;

    const float2* __restrict__ zr = (const float2*)pred_vel + (size_t)row * T_LEN;
    const float2* __restrict__ wr = (const float2*)targ_vel + (size_t)row * T_LEN;

    const float qv = __ldg(q_vel_p);
    const float r  = __ldg(r_vel_p);

    // ============ front-batch EVERY load, ALL perfectly coalesced ============
    float4 z0, z1, z2, z3, w0, w1, w2, w3;
    float2 hz;                               // halo (chunk>0)
    float2 tz0, tz1, tz2, tz3;               // table z       (chunk 0)
    float2 tw0, tw1, tw2, tw3;               // table w@t+1   (chunk 0)

    if (chunk == 0) {
        tz0 = zr[lane];          tz1 = zr[32 + lane];
        tz2 = zr[64 + lane];     tz3 = zr[96 + lane];
        tw0 = wr[lane + 1];      tw1 = wr[32 + lane + 1];
        tw2 = wr[64 + lane + 1]; tw3 = wr[96 + lane + 1];
        const float4* z4 = (const float4*)zr;
        const float4* w4 = (const float4*)wr;
        z2 = z4[64 + lane]; z3 = z4[96 + lane];     // steps [128,192) [192,256)
        w2 = w4[64 + lane]; w3 = w4[96 + lane];
    } else {
        const float4* z4 = (const float4*)(zr + c0);
        const float4* w4 = (const float4*)(wr + c0);
        z0 = z4[lane];      z1 = z4[32 + lane];
        z2 = z4[64 + lane]; z3 = z4[96 + lane];
        w0 = w4[lane];      w1 = w4[32 + lane];
        w2 = w4[64 + lane]; w3 = w4[96 + lane];
        hz = zr[c0 - 32 + lane];
    }

    // ============ steady-state gains: closed form ============
    const float cp = 0.5f * (qv + sqrtf(fmaf(qv, qv, 4.0f * qv * r)));
    const float K1 = __fdividef(cp, cp + r);
    const float K0 = DT * (1.0f - __fdividef(qv, cp));

    const float dss  = 1.0f - K1;          // v <- dss*v + K1*z
    const float Ass  = DT - K0;            // e = Ass*v - DT*w1 + K0*z1
    const float dss2 = dss * dss, dss4 = dss2 * dss2;
    const float e2  = dss4 * dss4;         // dss^8
    const float e4  = e2 * e2;             // dss^16
    const float e8  = e4 * e4;             // dss^32
    float dl2 = 1.0f;                      // dss^(2*lane): carry-injection weight
    if (lane & 1)  dl2 *= dss2;
    if (lane & 2)  dl2 *= dss4;
    if (lane & 4)  dl2 *= e2;
    if (lane & 8)  dl2 *= e4;
    if (lane & 16) dl2 *= e8;

    float acc = 0.0f;

    if (chunk == 0) {
        // ================== scalar chunk-0 path (64 blocks; verified) ==================
        float cx = 0.0f, cy = 0.0f;
        const float c_xy = RS * r, c_xq = RS * qv * r, c_yy = RS * (qv + r), c_u = RS * r;
        float x = 1.0f, y = 1.0f, u = 0.0f;
        for (int t = 0; t < lane; ++t) {
            float xn = fmaf(c_xq, y, c_xy * x);
            float yn = fmaf(c_yy, y, RS * x);
            float un = c_u * fmaf(DT, x, u);
            x = xn; y = yn; u = un;
        }
        float k1t[4], k0t[4];                       // gains at t = 32*it + lane
        #pragma unroll
        for (int it = 0; it < 4; ++it) {
            float xs = x, ys = y, us = u;
            { float xn = fmaf(c_xq, y, c_xy * x);
              float yn = fmaf(c_yy, y, RS * x);
              float un = c_u * fmaf(DT, x, u);
              x = xn; y = yn; u = un; }
            float inv = __fdividef(RS, y);
            k1t[it] = fmaf(qv, ys, xs) * inv;
            k0t[it] = fmaf(DT, xs, us) * inv;
            if (it < 3)
                for (int t = 0; t < 31; ++t) {
                    float xn = fmaf(c_xq, y, c_xy * x);
                    float yn = fmaf(c_yy, y, RS * x);
                    float un = c_u * fmaf(DT, x, u);
                    x = xn; y = yn; u = un;
                }
        }

        #pragma unroll
        for (int it = 0; it < 4; ++it) {
            float2 z  = (it == 0) ? tz0 : (it == 1) ? tz1 : (it == 2) ? tz2 : tz3;
            float2 w1 = (it == 0) ? tw0 : (it == 1) ? tw1 : (it == 2) ? tw2 : tw3;
            float K1v = k1t[it];
            float p   = 1.0f - K1v;
            float sx = K1v * z.x, sy = K1v * z.y;
            #pragma unroll
            for (int o = 1; o < 32; o <<= 1) {
                float ax = shup(sx, o), ay = shup(sy, o), ap = shup(p, o);
                if (lane >= o) { sx = fmaf(p, ax, sx); sy = fmaf(p, ay, sy); p *= ap; }
            }
            float vx = fmaf(p, cx, sx);
            float vy = fmaf(p, cy, sy);
            cx = bcast(vx, 31); cy = bcast(vy, 31);

            float k0n = shdn(k0t[it], 1);
            float k0w = (it < 3) ? bcast(k0t[it + 1], 0) : K0;
            float z1x = shdn(z.x, 1), z1y = shdn(z.y, 1);
            float zwx = (it == 0) ? bcast(tz1.x, 0) : (it == 1) ? bcast(tz2.x, 0)
                      : (it == 2) ? bcast(tz3.x, 0) : bcast(z2.x, 0);
            float zwy = (it == 0) ? bcast(tz1.y, 0) : (it == 1) ? bcast(tz2.y, 0)
                      : (it == 2) ? bcast(tz3.y, 0) : bcast(z2.y, 0);
            if (lane == 31) { k0n = k0w; z1x = zwx; z1y = zwy; }
            float an = DT - k0n;

            float ex = fmaf(an, vx, fmaf(-DT, w1.x, k0n * z1x));
            float ey = fmaf(an, vy, fmaf(-DT, w1.y, k0n * z1y));
            if (!(it == 3 && lane == 31)) {
                acc = fmaf(ex, ex, acc);
                acc = fmaf(ey, ey, acc);
            }
        }
        // scalar steady subtiles [128,192) [192,256): errors [127,255)
        #pragma unroll
        for (int s = 0; s < 2; ++s) {
            float4 Z = (s == 0) ? z2 : z3;
            float4 W = (s == 0) ? w2 : w3;
            float s0x = K1 * Z.x, s0y = K1 * Z.y;
            float s1x = fmaf(dss, s0x, K1 * Z.z), s1y = fmaf(dss, s0y, K1 * Z.w);
            float Sx = s1x, Sy = s1y, t_;
            t_ = shup(Sx, 1); if (lane >= 1) Sx = fmaf(dss2, t_, Sx);
            t_ = shup(Sy, 1); if (lane >= 1) Sy = fmaf(dss2, t_, Sy);
            t_ = shup(Sx, 2); if (lane >= 2) Sx = fmaf(dss4, t_, Sx);
            t_ = shup(Sy, 2); if (lane >= 2) Sy = fmaf(dss4, t_, Sy);
            t_ = shup(Sx, 4); if (lane >= 4) Sx = fmaf(e2, t_, Sx);
            t_ = shup(Sy, 4); if (lane >= 4) Sy = fmaf(e2, t_, Sy);
            t_ = shup(Sx, 8); if (lane >= 8) Sx = fmaf(e4, t_, Sx);
            t_ = shup(Sy, 8); if (lane >= 8) Sy = fmaf(e4, t_, Sy);
            float Px = shup(Sx, 1), Py = shup(Sy, 1);
            if (lane == 0) { Px = 0.0f; Py = 0.0f; }
            float prx = fmaf(dl2, cx, Px);
            float pry = fmaf(dl2, cy, Py);
            cx = bcast(Sx, 31); cy = bcast(Sy, 31);
            float v0x = fmaf(dss, prx, s0x), v0y = fmaf(dss, pry, s0y);
            float ex_, ey_;
            ex_ = fmaf(Ass, prx, fmaf(-DT, W.x, K0 * Z.x));
            ey_ = fmaf(Ass, pry, fmaf(-DT, W.y, K0 * Z.y));
            acc = fmaf(ex_, ex_, acc); acc = fmaf(ey_, ey_, acc);
            ex_ = fmaf(Ass, v0x, fmaf(-DT, W.z, K0 * Z.z));
            ey_ = fmaf(Ass, v0y, fmaf(-DT, W.w, K0 * Z.w));
            acc = fmaf(ex_, ex_, acc); acc = fmaf(ey_, ey_, acc);
        }
    } else {
        // ================== packed f32x2 steady path (960 blocks) ==================
        // per-lane PRE-MASKED scan coefficients: lane<o -> 0 (shfl-up returns own
        // value out of range; x0 annihilates it -> no predicates in the scan)
        const u64 K1p  = dup2(K1);
        const u64 dssp = dup2(dss);
        const u64 Assp = dup2(Ass);
        const u64 mDTp = dup2(-DT);
        const u64 K0p  = dup2(K0);
        const u64 dl2p = dup2(dl2);
        const u64 c1p  = dup2(lane >= 1 ? dss2 : 0.0f);
        const u64 c2p  = dup2(lane >= 2 ? dss4 : 0.0f);
        const u64 c4p  = dup2(lane >= 4 ? e2   : 0.0f);
        const u64 c8p  = dup2(lane >= 8 ? e4   : 0.0f);
        const u64 m0p  = dup2(lane == 0 ? 0.0f : 1.0f);

        // ---- halo: 32-step packed scan -> carry C = v_{c0-1} ----
        u64 C;
        {
            u64 S = mul2(K1p, pk2(hz.x, hz.y));
            S = fma2(dup2(lane >= 1  ? dss  : 0.0f), shup64(S, 1),  S);
            S = fma2(c1p,                          shup64(S, 2),  S);   // dss^2
            S = fma2(c2p,                          shup64(S, 4),  S);   // dss^4
            S = fma2(dup2(lane >= 8  ? e2   : 0.0f), shup64(S, 8),  S); // dss^8
            S = fma2(dup2(lane >= 16 ? e4   : 0.0f), shup64(S, 16), S); // dss^16
            C = bc64(S, 31);
        }

        u64 acc2 = 0;   // packed (x,y) accumulator (0x0 == (0.f,0.f))

        // ---- 4 packed 64-step subtiles: errors [c0-1, c0+255) ----
        #define STEADY64P(Z, W)                                                           \
        {                                                                                 \
            u64 zlo = pk2((Z).x, (Z).y), zhi = pk2((Z).z, (Z).w);                         \
            u64 wlo = pk2((W).x, (W).y), whi = pk2((W).z, (W).w);                         \
            u64 s0 = mul2(K1p, zlo);                                                      \
            u64 s1 = fma2(dssp, s0, mul2(K1p, zhi));                                      \
            u64 S = s1;                                                                   \
            S = fma2(c1p, shup64(S, 1), S);                                               \
            S = fma2(c2p, shup64(S, 2), S);                                               \
            S = fma2(c4p, shup64(S, 4), S);                                               \
            S = fma2(c8p, shup64(S, 8), S);                                               \
            u64 P  = mul2(m0p, shup64(S, 1));                                             \
            u64 pr = fma2(dl2p, C, P);            /* v at i0-1 */                         \
            C = bc64(S, 31);                                                              \
            u64 v0 = fma2(dssp, pr, s0);                                                  \
            u64 e0 = fma2(Assp, pr, fma2(mDTp, wlo, mul2(K0p, zlo)));                     \
            acc2 = fma2(e0, e0, acc2);                                                    \
            u64 e1 = fma2(Assp, v0, fma2(mDTp, whi, mul2(K0p, zhi)));                     \
            acc2 = fma2(e1, e1, acc2);                                                    \
        }

        STEADY64P(z0, w0)
        STEADY64P(z1, w1)
        STEADY64P(z2, w2)
        STEADY64P(z3, w3)
        #undef STEADY64P

        float ax, ay;
        unpk2(acc2, ax, ay);
        acc = ax + ay;
    }

    // ============ reduction ============
    #pragma unroll
    for (int o = 16; o > 0; o >>= 1)
        acc += __shfl_xor_sync(0xffffffffu, acc, o);
    if (lane == 0) swsum[wid] = acc;
    __syncthreads();

    if (tid == 0) {
        float bs = 0.0f;
        #pragma unroll
        for (int i = 0; i < WPB; ++i) bs += swsum[i];

        atomicAdd(&g_sum, (double)bs);
        __threadfence();
        unsigned c = atomicAdd(&g_cnt, 1u);
        if (c == gridDim.x - 1) {
            double s = atomicAdd(&g_sum, 0.0);        // coherent read (includes own add)
            const double cnt = (double)BATCH * (double)(T_LEN - 1) * 2.0;
            out[0] = (float)(s / cnt);
            g_sum = 0.0;                              // reset for next graph replay
            g_cnt = 0u;
        }
    }
}

extern "C" void kernel_launch(void* const* d_in, const int* in_sizes, int n_in,
                              void* d_out, int out_size)
{
    const float* pred_vel = (const float*)d_in[0];   // (B, T, 2)
    const float* targ_vel = (const float*)d_in[1];   // (B, T, 2)
    // d_in[2] = q_pos (never feeds the gain recursion)
    const float* q_vel    = (const float*)d_in[3];
    const float* r_vel    = (const float*)d_in[4];
    // d_in[5] = p0 (cancels in the windowed position difference)
    float* out = (float*)d_out;

    const int nblocks = NC0BLK + (BATCH * 15) / WPB;   // 64 + 960 = 1024 blocks
    kf_loss_kernel<<<nblocks, NTHR>>>(pred_vel, targ_vel, q_vel, r_vel, out);
}